// round 16
// baseline (speedup 1.0000x reference)
#include <cuda_runtime.h>
#include <cuda_bf16.h>
#include <cstdint>

#define NN 50000
#define DD 128
#define D2 256
#define NE 600000
#define NL 5
#define MT1 391  // gemm1 M-tiles
#define PGRID 148

// ---------------- device scratch ----------------
__device__ __align__(16) float g_h[NN * DD];
__device__ __align__(16) float g_y[NN * D2];
__device__ __align__(16) float g_v[NN * DD];
__device__ float g_s1[2][2 * D2];
__device__ float g_s2[2][2 * DD];
__device__ __align__(16) __nv_bfloat16 g_w1h[NL * D2 * DD];
__device__ __align__(16) __nv_bfloat16 g_w1l[NL * D2 * DD];
__device__ __align__(16) __nv_bfloat16 g_w2h[NL * DD * D2];
__device__ __align__(16) __nv_bfloat16 g_w2l[NL * DD * D2];
__device__ int g_cnt[NN];
__device__ int g_cnt2[NN];
__device__ int g_scan[NN];
__device__ int g_bsum[128];
__device__ int g_rowptr[NN];
__device__ int g_csrc[NE];
__device__ int g_ca[NE];

// ---------------- mma / ldmatrix wrappers ----------------
__device__ __forceinline__ void mma16816(float* c, const uint32_t* a, const uint32_t* b) {
    asm volatile(
        "mma.sync.aligned.m16n8k16.row.col.f32.bf16.bf16.f32 "
        "{%0,%1,%2,%3}, {%4,%5,%6,%7}, {%8,%9}, {%0,%1,%2,%3};"
        : "+f"(c[0]), "+f"(c[1]), "+f"(c[2]), "+f"(c[3])
        : "r"(a[0]), "r"(a[1]), "r"(a[2]), "r"(a[3]), "r"(b[0]), "r"(b[1]));
}

__device__ __forceinline__ void ldsm4(uint32_t* r, uint32_t a) {
    asm volatile("ldmatrix.sync.aligned.m8n8.x4.shared.b16 {%0,%1,%2,%3}, [%4];"
                 : "=r"(r[0]), "=r"(r[1]), "=r"(r[2]), "=r"(r[3])
                 : "r"(a));
}

__device__ __forceinline__ void split8(const float* v, uint4& hi, uint4& lo) {
    uint32_t h[8], l[8];
#pragma unroll
    for (int i = 0; i < 8; i++) {
        __nv_bfloat16 hb = __float2bfloat16(v[i]);
        float         r  = v[i] - __bfloat162float(hb);
        __nv_bfloat16 lb = __float2bfloat16(r);
        h[i]             = (uint32_t)__bfloat16_as_ushort(hb);
        l[i]             = (uint32_t)__bfloat16_as_ushort(lb);
    }
    hi = make_uint4(h[0] | (h[1] << 16), h[2] | (h[3] << 16), h[4] | (h[5] << 16),
                    h[6] | (h[7] << 16));
    lo = make_uint4(l[0] | (l[1] << 16), l[2] | (l[3] << 16), l[4] | (l[5] << 16),
                    l[6] | (l[7] << 16));
}

__device__ __forceinline__ void split4(const float* v, uint2& hi, uint2& lo) {
    uint32_t h[4], l[4];
#pragma unroll
    for (int i = 0; i < 4; i++) {
        __nv_bfloat16 hb = __float2bfloat16(v[i]);
        float         r  = v[i] - __bfloat162float(hb);
        __nv_bfloat16 lb = __float2bfloat16(r);
        h[i]             = (uint32_t)__bfloat16_as_ushort(hb);
        l[i]             = (uint32_t)__bfloat16_as_ushort(lb);
    }
    hi = make_uint2(h[0] | (h[1] << 16), h[2] | (h[3] << 16));
    lo = make_uint2(l[0] | (l[1] << 16), l[2] | (l[3] << 16));
}

// ---------------- atom encoder ----------------
__global__ void atom_enc_kernel(const int* __restrict__ x, const float* __restrict__ emb) {
    int i = blockIdx.x * blockDim.x + threadIdx.x;
    int n = i >> 7;
    int d = i & 127;
    float s = 0.f;
#pragma unroll
    for (int k = 0; k < 9; k++) {
        int v = x[n * 9 + k];
        s += emb[((size_t)(k * 128 + v)) * 128 + d];
    }
    g_h[i] = s;
}

// ---------------- CSR build ----------------
__global__ void hist_kernel(const int* __restrict__ ei) {
    int e = blockIdx.x * blockDim.x + threadIdx.x;
    if (e < NE) atomicAdd(&g_cnt[ei[NE + e]], 1);
}
__global__ void scan1_kernel() {
    __shared__ int sh[512];
    int i           = blockIdx.x * 512 + threadIdx.x;
    int v           = (i < NN) ? g_cnt[i] : 0;
    sh[threadIdx.x] = v;
    __syncthreads();
#pragma unroll
    for (int o = 1; o < 512; o <<= 1) {
        int t = (threadIdx.x >= o) ? sh[threadIdx.x - o] : 0;
        __syncthreads();
        sh[threadIdx.x] += t;
        __syncthreads();
    }
    if (i < NN) g_scan[i] = sh[threadIdx.x];
    if (threadIdx.x == 511) g_bsum[blockIdx.x] = sh[511];
}
__global__ void scan3_kernel() {
    __shared__ int soff;
    int b = blockIdx.x >> 1;
    if (threadIdx.x == 0) {
        int run = 0;
        for (int k = 0; k < b; k++) run += g_bsum[k];
        soff = run;
    }
    __syncthreads();
    int i = blockIdx.x * blockDim.x + threadIdx.x;
    if (i < NN) {
        g_rowptr[i] = g_scan[i] - g_cnt[i] + soff;
        g_cnt2[i]   = 0;
    }
}
__global__ void fill_kernel(const int* __restrict__ ei, const int* __restrict__ ea) {
    int e = blockIdx.x * blockDim.x + threadIdx.x;
    if (e >= NE) return;
    int dst     = ei[NE + e];
    int slot    = atomicAdd(&g_cnt2[dst], 1);
    int idx     = g_rowptr[dst] + slot;
    g_csrc[idx] = ei[e];
    g_ca[idx]   = ea[e * 3] | (ea[e * 3 + 1] << 4) | (ea[e * 3 + 2] << 8);
}

// ---------------- weight prep + initial zeros ----------------
__global__ void wprep_all_kernel(const float* __restrict__ W1, const float* __restrict__ W2) {
    int i = blockIdx.x * blockDim.x + threadIdx.x;
    if (blockIdx.x == 0 && threadIdx.x < 512) g_s1[0][threadIdx.x] = 0.f;
    if (i < NN) g_cnt[i] = 0;
    int l = i >> 16;
    int j = i & 65535;
    if (j < 32768) {
        int   k = j >> 8;
        int   n = j & 255;
        float w = W1[l * 32768 + j];
        __nv_bfloat16 hb = __float2bfloat16(w);
        __nv_bfloat16 lb = __float2bfloat16(w - __bfloat162float(hb));
        g_w1h[l * 32768 + n * DD + k] = hb;
        g_w1l[l * 32768 + n * DD + k] = lb;
    } else {
        int   jj = j - 32768;
        int   k  = jj >> 7;
        int   n  = jj & 127;
        float w  = W2[l * 32768 + jj];
        __nv_bfloat16 hb = __float2bfloat16(w);
        __nv_bfloat16 lb = __float2bfloat16(w - __bfloat162float(hb));
        g_w2h[l * 32768 + n * D2 + k] = hb;
        g_w2l[l * 32768 + n * D2 + k] = lb;
    }
}

// ---------------- gather helper ----------------
__device__ __forceinline__ float4 bnrelu4(float4 h, float4 sc, float4 sh) {
    h.x = fmaxf(h.x * sc.x + sh.x, 0.f);
    h.y = fmaxf(h.y * sc.y + sh.y, 0.f);
    h.z = fmaxf(h.z * sc.z + sh.z, 0.f);
    h.w = fmaxf(h.w * sc.w + sh.w, 0.f);
    return h;
}

// =================================================================================
// GEMM1 (PERSISTENT fused gather + HMMA + LDSM), 1024 threads / 32 warps.
// Warp tile 32x32 (acc[2][4][4]); gather: 4 nodes per warp -> 2x latency hiding.
// =================================================================================
#define SA1 136
#define G1_ALO 34816
#define G1_BHI 69632
#define G1_BLO 139264
#define G1_BOND 208896
#define G1_SC 221184
#define G1_SH 221696
#define G1_SMEM 222208

template <int APPLY_BN>
__global__ void __launch_bounds__(1024, 1)
gemm1_tc(const float* __restrict__ bias, const float* __restrict__ eps_l,
         const float* __restrict__ bemb_l, const float* __restrict__ gp,
         const float* __restrict__ bp, int layer, int p) {
    extern __shared__ char sm[];
    __nv_bfloat16* sAh   = (__nv_bfloat16*)sm;
    __nv_bfloat16* sAl   = (__nv_bfloat16*)(sm + G1_ALO);
    __nv_bfloat16* sBh   = (__nv_bfloat16*)(sm + G1_BHI);
    __nv_bfloat16* sBl   = (__nv_bfloat16*)(sm + G1_BLO);
    float*         sbond = (float*)(sm + G1_BOND);
    float*         ssc   = (float*)(sm + G1_SC);
    float*         ssh   = (float*)(sm + G1_SH);

    const __nv_bfloat16* wh = g_w1h + layer * 32768;
    const __nv_bfloat16* wl = g_w1l + layer * 32768;

    const int t    = threadIdx.x;
    const int lane = t & 31;
    const int wid  = t >> 5;  // 0..31
    const int gid  = lane >> 2;
    const int q    = lane & 3;

    if (APPLY_BN && t < DD) {
        float mu   = g_s2[1 - p][t] * (1.f / NN);
        float var  = g_s2[1 - p][DD + t] * (1.f / NN) - mu * mu;
        float istd = rsqrtf(var + 1e-5f);
        float s    = gp[t] * istd;
        ssc[t]     = s;
        ssh[t]     = bp[t] - mu * s;
    }
    if (blockIdx.x == 0 && t < 256) g_s2[p][t] = 0.f;
    if (t < 768) ((float4*)sbond)[t] = ((const float4*)bemb_l)[t];

    // --- stage B once ---
#pragma unroll
    for (int i = 0; i < 4; i++) {
        int idx = i * 1024 + t;
        int n   = idx >> 4;
        int k0  = (idx & 15) * 8;
        *(uint4*)(sBh + n * SA1 + k0) = *(const uint4*)(wh + n * DD + k0);
        *(uint4*)(sBl + n * SA1 + k0) = *(const uint4*)(wl + n * DD + k0);
    }
    __syncthreads();

    const float* src = APPLY_BN ? g_v : g_h;
    float        ep  = 1.f + eps_l[0];
    float4       sc4, sh4;
    if (APPLY_BN) {
        sc4 = ((const float4*)ssc)[lane];
        sh4 = ((const float4*)ssh)[lane];
    }

    const int wm = wid & 3;   // 32-row quadrant
    const int wn = wid >> 2;  // 0..7, 32-col group

    const uint32_t sAh32 = (uint32_t)__cvta_generic_to_shared(sAh);
    const uint32_t sAl32 = (uint32_t)__cvta_generic_to_shared(sAl);
    const uint32_t sBh32 = (uint32_t)__cvta_generic_to_shared(sBh);
    const uint32_t sBl32 = (uint32_t)__cvta_generic_to_shared(sBl);
    const uint32_t aoff =
        (uint32_t)((wm * 32 + (lane & 15)) * SA1 * 2 + (((lane >> 4) << 3) * 2));
    const uint32_t boff =
        (uint32_t)((wn * 32 + (lane & 7) + (((lane >> 4) & 1) << 3)) * SA1 * 2 +
                   ((((lane >> 3) & 1) << 3) * 2));

#pragma unroll 1
    for (int tile = blockIdx.x; tile < MT1; tile += gridDim.x) {
        const int row0 = tile * 128;

        // --- gather -> stage A (each warp 4 nodes; 4-way MLP + index prefetch) ---
#pragma unroll 1
        for (int j = 0; j < 4; j++) {
            int    r    = wid * 4 + j;
            int    node = row0 + r;
            float4 acc  = make_float4(0.f, 0.f, 0.f, 0.f);
            if (node < NN) {
                acc = ((const float4*)(src + (size_t)node * DD))[lane];
                if (APPLY_BN) acc = bnrelu4(acc, sc4, sh4);
                acc.x *= ep;
                acc.y *= ep;
                acc.z *= ep;
                acc.w *= ep;
                int start = g_rowptr[node];
                int deg   = g_cnt[node];
                int nb4   = deg >> 2;
                int cs[4], cb[4];
                if (nb4 > 0) {
#pragma unroll
                    for (int u = 0; u < 4; u++) {
                        cs[u] = g_csrc[start + u];
                        cb[u] = g_ca[start + u];
                    }
                }
#pragma unroll 1
                for (int b = 0; b < nb4; b++) {
                    int ns[4], na[4];
                    if (b + 1 < nb4) {
                        int o = start + (b + 1) * 4;
#pragma unroll
                        for (int u = 0; u < 4; u++) {
                            ns[u] = g_csrc[o + u];
                            na[u] = g_ca[o + u];
                        }
                    }
                    float4 hv[4];
#pragma unroll
                    for (int u = 0; u < 4; u++)
                        hv[u] = ((const float4*)(src + (size_t)cs[u] * DD))[lane];
#pragma unroll
                    for (int u = 0; u < 4; u++) {
                        float4 h = hv[u];
                        int    a = cb[u];
                        if (APPLY_BN) h = bnrelu4(h, sc4, sh4);
                        float4 e0 = ((const float4*)(sbond + (a & 15) * DD))[lane];
                        float4 e1 = ((const float4*)(sbond + (8 + ((a >> 4) & 15)) * DD))[lane];
                        float4 e2 = ((const float4*)(sbond + (16 + ((a >> 8) & 15)) * DD))[lane];
                        acc.x += fmaxf(h.x + e0.x + e1.x + e2.x, 0.f);
                        acc.y += fmaxf(h.y + e0.y + e1.y + e2.y, 0.f);
                        acc.z += fmaxf(h.z + e0.z + e1.z + e2.z, 0.f);
                        acc.w += fmaxf(h.w + e0.w + e1.w + e2.w, 0.f);
                    }
                    if (b + 1 < nb4) {
#pragma unroll
                        for (int u = 0; u < 4; u++) {
                            cs[u] = ns[u];
                            cb[u] = na[u];
                        }
                    }
                }
                for (int jj = nb4 * 4; jj < deg; jj++) {
                    int    s = g_csrc[start + jj];
                    int    a = g_ca[start + jj];
                    float4 h = ((const float4*)(src + (size_t)s * DD))[lane];
                    if (APPLY_BN) h = bnrelu4(h, sc4, sh4);
                    float4 e0 = ((const float4*)(sbond + (a & 15) * DD))[lane];
                    float4 e1 = ((const float4*)(sbond + (8 + ((a >> 4) & 15)) * DD))[lane];
                    float4 e2 = ((const float4*)(sbond + (16 + ((a >> 8) & 15)) * DD))[lane];
                    acc.x += fmaxf(h.x + e0.x + e1.x + e2.x, 0.f);
                    acc.y += fmaxf(h.y + e0.y + e1.y + e2.y, 0.f);
                    acc.z += fmaxf(h.z + e0.z + e1.z + e2.z, 0.f);
                    acc.w += fmaxf(h.w + e0.w + e1.w + e2.w, 0.f);
                }
            }
            uint2 hi, lo;
            split4(&acc.x, hi, lo);
            *(uint2*)(sAh + r * SA1 + lane * 4) = hi;
            *(uint2*)(sAl + r * SA1 + lane * 4) = lo;
        }
        __syncthreads();

        float acc[2][4][4];
#pragma unroll
        for (int m = 0; m < 2; m++)
#pragma unroll
            for (int nf = 0; nf < 4; nf++)
#pragma unroll
                for (int j = 0; j < 4; j++) acc[m][nf][j] = 0.f;

#pragma unroll
        for (int ks = 0; ks < 8; ks++) {
            uint32_t kb = (uint32_t)(ks * 32);
            uint32_t ah[2][4], al[2][4];
            ldsm4(ah[0], sAh32 + aoff + kb);
            ldsm4(ah[1], sAh32 + aoff + 16 * SA1 * 2 + kb);
            ldsm4(al[0], sAl32 + aoff + kb);
            ldsm4(al[1], sAl32 + aoff + 16 * SA1 * 2 + kb);
#pragma unroll
            for (int pp = 0; pp < 2; pp++) {
                uint32_t bh[4], bl[4];
                ldsm4(bh, sBh32 + boff + (uint32_t)(pp * 16 * SA1 * 2) + kb);
                ldsm4(bl, sBl32 + boff + (uint32_t)(pp * 16 * SA1 * 2) + kb);
#pragma unroll
                for (int m = 0; m < 2; m++) {
                    mma16816(acc[m][2 * pp], ah[m], bh);
                    mma16816(acc[m][2 * pp], ah[m], bl);
                    mma16816(acc[m][2 * pp], al[m], bh);
                    mma16816(acc[m][2 * pp + 1], ah[m], bh + 2);
                    mma16816(acc[m][2 * pp + 1], ah[m], bl + 2);
                    mma16816(acc[m][2 * pp + 1], al[m], bh + 2);
                }
            }
        }

#pragma unroll
        for (int nf = 0; nf < 4; nf++) {
            int    c  = wn * 32 + nf * 8 + q * 2;
            float2 b2 = *(const float2*)(bias + c);
            float  sx = 0.f, sy = 0.f, qx = 0.f, qy = 0.f;
#pragma unroll
            for (int m = 0; m < 2; m++) {
                int r = row0 + wm * 32 + m * 16 + gid;
                if (r < NN) {
                    float vx = acc[m][nf][0] + b2.x;
                    float vy = acc[m][nf][1] + b2.y;
                    *(float2*)(g_y + (size_t)r * D2 + c) = make_float2(vx, vy);
                    sx += vx; sy += vy; qx += vx * vx; qy += vy * vy;
                }
                if (r + 8 < NN) {
                    float vx = acc[m][nf][2] + b2.x;
                    float vy = acc[m][nf][3] + b2.y;
                    *(float2*)(g_y + (size_t)(r + 8) * D2 + c) = make_float2(vx, vy);
                    sx += vx; sy += vy; qx += vx * vx; qy += vy * vy;
                }
            }
#pragma unroll
            for (int o = 4; o < 32; o <<= 1) {
                sx += __shfl_xor_sync(0xffffffff, sx, o);
                sy += __shfl_xor_sync(0xffffffff, sy, o);
                qx += __shfl_xor_sync(0xffffffff, qx, o);
                qy += __shfl_xor_sync(0xffffffff, qy, o);
            }
            if (gid == 0) {
                atomicAdd(&g_s1[p][c], sx);
                atomicAdd(&g_s1[p][c + 1], sy);
                atomicAdd(&g_s1[p][D2 + c], qx);
                atomicAdd(&g_s1[p][D2 + c + 1], qy);
            }
        }
        __syncthreads();
    }
}

// =================================================================================
// GEMM2 (HMMA+LDSM): unchanged from R15 baseline.
// =================================================================================
#define SA2 264
#define G2_ALO 67584
#define G2_B 135168
#define G2_SC 202752
#define G2_SH 203776
#define G2_SMEM 204800

__global__ void __launch_bounds__(512, 1)
gemm2_tc(const float* __restrict__ bias, const float* __restrict__ g1p,
         const float* __restrict__ be1p, int layer, int p) {
    extern __shared__ char sm[];
    __nv_bfloat16* sAh = (__nv_bfloat16*)sm;
    __nv_bfloat16* sAl = (__nv_bfloat16*)(sm + G2_ALO);
    __nv_bfloat16* sB  = (__nv_bfloat16*)(sm + G2_B);
    float*         sSC = (float*)(sm + G2_SC);
    float*         sSH = (float*)(sm + G2_SH);

    const __nv_bfloat16* wh = g_w2h + layer * 32768;
    const __nv_bfloat16* wl = g_w2l + layer * 32768;

    const int t    = threadIdx.x;
    const int lane = t & 31;
    const int wid  = t >> 5;
    const int row0 = blockIdx.x * 128;
    const int gid  = lane >> 2;
    const int q    = lane & 3;

    if (t < 256) {
        float mu   = g_s1[p][t] * (1.f / NN);
        float var  = g_s1[p][D2 + t] * (1.f / NN) - mu * mu;
        float istd = rsqrtf(var + 1e-5f);
        float s    = g1p[t] * istd;
        sSC[t]     = s;
        sSH[t]     = be1p[t] - mu * s;
    }
    if (blockIdx.x == 0) g_s1[1 - p][t] = 0.f;
    __syncthreads();

    {
        int          r     = t >> 2;
        int          qq    = t & 3;
        const float* rp    = g_y + (size_t)(row0 + r) * D2;
        bool         valid = (row0 + r) < NN;
#pragma unroll
        for (int j = 0; j < 8; j++) {
            int   k0 = qq * 64 + j * 8;
            float v[8];
            if (valid) {
                float4 a = ((const float4*)rp)[k0 >> 2];
                float4 b = ((const float4*)rp)[(k0 >> 2) + 1];
                float  raw[8] = {a.x, a.y, a.z, a.w, b.x, b.y, b.z, b.w};
#pragma unroll
                for (int i = 0; i < 8; i++)
                    v[i] = fmaxf(raw[i] * sSC[k0 + i] + sSH[k0 + i], 0.f);
            } else {
#pragma unroll
                for (int i = 0; i < 8; i++) v[i] = 0.f;
            }
            uint4 hi, lo;
            split8(v, hi, lo);
            *(uint4*)(sAh + r * SA2 + k0) = hi;
            *(uint4*)(sAl + r * SA2 + k0) = lo;
        }
    }
#pragma unroll
    for (int i = 0; i < 8; i++) {
        int idx = i * 512 + t;
        int n   = idx >> 5;
        int k0  = (idx & 31) * 8;
        *(uint4*)(sB + n * SA2 + k0) = *(const uint4*)(wh + n * D2 + k0);
    }
    __syncthreads();

    const int wm = wid & 3;
    const int wn = wid >> 2;

    const uint32_t sAh32 = (uint32_t)__cvta_generic_to_shared(sAh);
    const uint32_t sAl32 = (uint32_t)__cvta_generic_to_shared(sAl);
    const uint32_t sB32  = (uint32_t)__cvta_generic_to_shared(sB);
    const uint32_t aoff =
        (uint32_t)((wm * 32 + (lane & 15)) * SA2 * 2 + (((lane >> 4) << 3) * 2));
    const uint32_t boff =
        (uint32_t)((wn * 32 + (lane & 7) + (((lane >> 4) & 1) << 3)) * SA2 * 2 +
                   ((((lane >> 3) & 1) << 3) * 2));

    float acc[2][4][4];
#pragma unroll
    for (int m = 0; m < 2; m++)
#pragma unroll
        for (int nf = 0; nf < 4; nf++)
#pragma unroll
            for (int j = 0; j < 4; j++) acc[m][nf][j] = 0.f;

#pragma unroll
    for (int ks = 0; ks < 16; ks++) {
        uint32_t kb = (uint32_t)(ks * 32);
        uint32_t ah[2][4], al[2][4];
        ldsm4(ah[0], sAh32 + aoff + kb);
        ldsm4(ah[1], sAh32 + aoff + 16 * SA2 * 2 + kb);
        ldsm4(al[0], sAl32 + aoff + kb);
        ldsm4(al[1], sAl32 + aoff + 16 * SA2 * 2 + kb);
#pragma unroll
        for (int pp = 0; pp < 2; pp++) {
            uint32_t bh[4];
            ldsm4(bh, sB32 + boff + (uint32_t)(pp * 16 * SA2 * 2) + kb);
#pragma unroll
            for (int m = 0; m < 2; m++) {
                mma16816(acc[m][2 * pp], ah[m], bh);
                mma16816(acc[m][2 * pp], al[m], bh);
                mma16816(acc[m][2 * pp + 1], ah[m], bh + 2);
                mma16816(acc[m][2 * pp + 1], al[m], bh + 2);
            }
        }
    }

    __syncthreads();
#pragma unroll
    for (int i = 0; i < 8; i++) {
        int idx = i * 512 + t;
        int n   = idx >> 5;
        int k0  = (idx & 31) * 8;
        *(uint4*)(sB + n * SA2 + k0) = *(const uint4*)(wl + n * D2 + k0);
    }
    __syncthreads();

#pragma unroll
    for (int ks = 0; ks < 16; ks++) {
        uint32_t kb = (uint32_t)(ks * 32);
        uint32_t ah[2][4];
        ldsm4(ah[0], sAh32 + aoff + kb);
        ldsm4(ah[1], sAh32 + aoff + 16 * SA2 * 2 + kb);
#pragma unroll
        for (int pp = 0; pp < 2; pp++) {
            uint32_t bl[4];
            ldsm4(bl, sB32 + boff + (uint32_t)(pp * 16 * SA2 * 2) + kb);
#pragma unroll
            for (int m = 0; m < 2; m++) {
                mma16816(acc[m][2 * pp], ah[m], bl);
                mma16816(acc[m][2 * pp + 1], ah[m], bl + 2);
            }
        }
    }

#pragma unroll
    for (int nf = 0; nf < 4; nf++) {
        int    c  = wn * 32 + nf * 8 + q * 2;
        float2 b2 = *(const float2*)(bias + c);
        float  sx = 0.f, sy = 0.f, qx = 0.f, qy = 0.f;
#pragma unroll
        for (int m = 0; m < 2; m++) {
            int r = row0 + wm * 32 + m * 16 + gid;
            if (r < NN) {
                float vx = acc[m][nf][0] + b2.x;
                float vy = acc[m][nf][1] + b2.y;
                *(float2*)(g_v + (size_t)r * DD + c) = make_float2(vx, vy);
                sx += vx; sy += vy; qx += vx * vx; qy += vy * vy;
            }
            if (r + 8 < NN) {
                float vx = acc[m][nf][2] + b2.x;
                float vy = acc[m][nf][3] + b2.y;
                *(float2*)(g_v + (size_t)(r + 8) * DD + c) = make_float2(vx, vy);
                sx += vx; sy += vy; qx += vx * vx; qy += vy * vy;
            }
        }
#pragma unroll
        for (int o = 4; o < 32; o <<= 1) {
            sx += __shfl_xor_sync(0xffffffff, sx, o);
            sy += __shfl_xor_sync(0xffffffff, sy, o);
            qx += __shfl_xor_sync(0xffffffff, qx, o);
            qy += __shfl_xor_sync(0xffffffff, qy, o);
        }
        if (gid == 0) {
            atomicAdd(&g_s2[p][c], sx);
            atomicAdd(&g_s2[p][c + 1], sy);
            atomicAdd(&g_s2[p][DD + c], qx);
            atomicAdd(&g_s2[p][DD + c + 1], qy);
        }
    }
}

// ---------------- final output ----------------
__global__ void norm_out_kernel(float* __restrict__ out, const float* __restrict__ gp,
                                const float* __restrict__ bp, int p) {
    __shared__ float ssc[DD], ssh[DD];
    int t = threadIdx.x;
    if (t < DD) {
        float mu   = g_s2[p][t] * (1.f / NN);
        float var  = g_s2[p][DD + t] * (1.f / NN) - mu * mu;
        float istd = rsqrtf(var + 1e-5f);
        float s    = gp[t] * istd;
        ssc[t]     = s;
        ssh[t]     = bp[t] - mu * s;
    }
    __syncthreads();
    const int total4 = NN * DD / 4;
    for (int i = blockIdx.x * blockDim.x + t; i < total4; i += gridDim.x * blockDim.x) {
        int    c4 = i & 31;
        float4 v  = ((const float4*)g_v)[i];
        float4 sc = ((const float4*)ssc)[c4];
        float4 sh = ((const float4*)ssh)[c4];
        v.x = v.x * sc.x + sh.x;
        v.y = v.y * sc.y + sh.y;
        v.z = v.z * sc.z + sh.z;
        v.w = v.w * sc.w + sh.w;
        ((float4*)out)[i] = v;
    }
}

// ---------------- launch ----------------
extern "C" void kernel_launch(void* const* d_in, const int* in_sizes, int n_in,
                              void* d_out, int out_size) {
    const int*   x    = (const int*)d_in[0];
    const int*   ei   = (const int*)d_in[1];
    const int*   ea   = (const int*)d_in[2];
    const float* aemb = (const float*)d_in[3];
    const float* bemb = (const float*)d_in[4];
    const float* W1   = (const float*)d_in[5];
    const float* b1   = (const float*)d_in[6];
    const float* g1   = (const float*)d_in[7];
    const float* be1  = (const float*)d_in[8];
    const float* W2   = (const float*)d_in[9];
    const float* b2   = (const float*)d_in[10];
    const float* eps  = (const float*)d_in[11];
    const float* gout = (const float*)d_in[12];
    const float* beo  = (const float*)d_in[13];
    float*       out  = (float*)d_out;

    cudaFuncSetAttribute(gemm1_tc<0>, cudaFuncAttributeMaxDynamicSharedMemorySize, G1_SMEM);
    cudaFuncSetAttribute(gemm1_tc<1>, cudaFuncAttributeMaxDynamicSharedMemorySize, G1_SMEM);
    cudaFuncSetAttribute(gemm2_tc, cudaFuncAttributeMaxDynamicSharedMemorySize, G2_SMEM);

    atom_enc_kernel<<<(NN * DD) / 256, 256>>>(x, aemb);
    wprep_all_kernel<<<640, 512>>>(W1, W2);

    const int NB = (NN + 511) / 512;
    hist_kernel<<<(NE + 255) / 256, 256>>>(ei);
    scan1_kernel<<<NB, 512>>>();
    scan3_kernel<<<(NN + 255) / 256, 256>>>();
    fill_kernel<<<(NE + 255) / 256, 256>>>(ei, ea);

    const int mblocks = (NN + 127) / 128;
    for (int l = 0; l < NL; l++) {
        int p = l & 1;
        if (l == 0)
            gemm1_tc<0><<<PGRID, 1024, G1_SMEM>>>(b1, eps, bemb, nullptr, nullptr, 0, 0);
        else
            gemm1_tc<1><<<PGRID, 1024, G1_SMEM>>>(b1 + l * D2, eps + l,
                                                  bemb + l * 3 * 8 * DD,
                                                  gout + (l - 1) * DD, beo + (l - 1) * DD,
                                                  l, p);
        gemm2_tc<<<mblocks, 512, G2_SMEM>>>(b2 + l * DD, g1 + l * D2, be1 + l * D2, l, p);
    }
    norm_out_kernel<<<256, 256>>>(out, gout + (NL - 1) * DD, beo + (NL - 1) * DD,
                                  (NL - 1) & 1);
}

// round 17
// speedup vs baseline: 1.0578x; 1.0578x over previous
#include <cuda_runtime.h>
#include <cuda_bf16.h>
#include <cstdint>

#define NN 50000
#define DD 128
#define D2 256
#define NE 600000
#define NL 5
#define MT1 391
#define PGRID 148

// ---------------- device scratch ----------------
__device__ __align__(16) float g_h[NN * DD];
__device__ __align__(16) float g_y[NN * D2];
__device__ __align__(16) float g_v[NN * DD];
__device__ float g_s1[2][2 * D2];
__device__ float g_s2[2][2 * DD];
__device__ __align__(16) __nv_bfloat16 g_w1h[NL * D2 * DD];
__device__ __align__(16) __nv_bfloat16 g_w1l[NL * D2 * DD];
__device__ __align__(16) __nv_bfloat16 g_w2h[NL * DD * D2];
__device__ __align__(16) __nv_bfloat16 g_w2l[NL * DD * D2];
__device__ int g_cnt[NN];
__device__ int g_cnt2[NN];
__device__ int g_scan[NN];
__device__ int g_bsum[128];
__device__ int g_rowptr[NN];
__device__ int g_csrc[NE];
__device__ int g_ca[NE];

// ---------------- mma / ldmatrix wrappers ----------------
__device__ __forceinline__ void mma16816(float* c, const uint32_t* a, const uint32_t* b) {
    asm volatile(
        "mma.sync.aligned.m16n8k16.row.col.f32.bf16.bf16.f32 "
        "{%0,%1,%2,%3}, {%4,%5,%6,%7}, {%8,%9}, {%0,%1,%2,%3};"
        : "+f"(c[0]), "+f"(c[1]), "+f"(c[2]), "+f"(c[3])
        : "r"(a[0]), "r"(a[1]), "r"(a[2]), "r"(a[3]), "r"(b[0]), "r"(b[1]));
}

__device__ __forceinline__ void ldsm4(uint32_t* r, uint32_t a) {
    asm volatile("ldmatrix.sync.aligned.m8n8.x4.shared.b16 {%0,%1,%2,%3}, [%4];"
                 : "=r"(r[0]), "=r"(r[1]), "=r"(r[2]), "=r"(r[3])
                 : "r"(a));
}

__device__ __forceinline__ void split8(const float* v, uint4& hi, uint4& lo) {
    uint32_t h[8], l[8];
#pragma unroll
    for (int i = 0; i < 8; i++) {
        __nv_bfloat16 hb = __float2bfloat16(v[i]);
        float         r  = v[i] - __bfloat162float(hb);
        __nv_bfloat16 lb = __float2bfloat16(r);
        h[i]             = (uint32_t)__bfloat16_as_ushort(hb);
        l[i]             = (uint32_t)__bfloat16_as_ushort(lb);
    }
    hi = make_uint4(h[0] | (h[1] << 16), h[2] | (h[3] << 16), h[4] | (h[5] << 16),
                    h[6] | (h[7] << 16));
    lo = make_uint4(l[0] | (l[1] << 16), l[2] | (l[3] << 16), l[4] | (l[5] << 16),
                    l[6] | (l[7] << 16));
}

__device__ __forceinline__ void split4(const float* v, uint2& hi, uint2& lo) {
    uint32_t h[4], l[4];
#pragma unroll
    for (int i = 0; i < 4; i++) {
        __nv_bfloat16 hb = __float2bfloat16(v[i]);
        float         r  = v[i] - __bfloat162float(hb);
        __nv_bfloat16 lb = __float2bfloat16(r);
        h[i]             = (uint32_t)__bfloat16_as_ushort(hb);
        l[i]             = (uint32_t)__bfloat16_as_ushort(lb);
    }
    hi = make_uint2(h[0] | (h[1] << 16), h[2] | (h[3] << 16));
    lo = make_uint2(l[0] | (l[1] << 16), l[2] | (l[3] << 16));
}

// ---------------- atom encoder ----------------
__global__ void atom_enc_kernel(const int* __restrict__ x, const float* __restrict__ emb) {
    int i = blockIdx.x * blockDim.x + threadIdx.x;
    int n = i >> 7;
    int d = i & 127;
    float s = 0.f;
#pragma unroll
    for (int k = 0; k < 9; k++) {
        int v = x[n * 9 + k];
        s += emb[((size_t)(k * 128 + v)) * 128 + d];
    }
    g_h[i] = s;
}

// ---------------- CSR build ----------------
__global__ void hist_kernel(const int* __restrict__ ei) {
    int e = blockIdx.x * blockDim.x + threadIdx.x;
    if (e < NE) atomicAdd(&g_cnt[ei[NE + e]], 1);
}
__global__ void scan1_kernel() {
    __shared__ int sh[512];
    int i           = blockIdx.x * 512 + threadIdx.x;
    int v           = (i < NN) ? g_cnt[i] : 0;
    sh[threadIdx.x] = v;
    __syncthreads();
#pragma unroll
    for (int o = 1; o < 512; o <<= 1) {
        int t = (threadIdx.x >= o) ? sh[threadIdx.x - o] : 0;
        __syncthreads();
        sh[threadIdx.x] += t;
        __syncthreads();
    }
    if (i < NN) g_scan[i] = sh[threadIdx.x];
    if (threadIdx.x == 511) g_bsum[blockIdx.x] = sh[511];
}
__global__ void scan3_kernel() {
    __shared__ int soff;
    int b = blockIdx.x >> 1;
    if (threadIdx.x == 0) {
        int run = 0;
        for (int k = 0; k < b; k++) run += g_bsum[k];
        soff = run;
    }
    __syncthreads();
    int i = blockIdx.x * blockDim.x + threadIdx.x;
    if (i < NN) {
        g_rowptr[i] = g_scan[i] - g_cnt[i] + soff;
        g_cnt2[i]   = 0;
    }
}
__global__ void fill_kernel(const int* __restrict__ ei, const int* __restrict__ ea) {
    int e = blockIdx.x * blockDim.x + threadIdx.x;
    if (e >= NE) return;
    int dst     = ei[NE + e];
    int slot    = atomicAdd(&g_cnt2[dst], 1);
    int idx     = g_rowptr[dst] + slot;
    g_csrc[idx] = ei[e];
    g_ca[idx]   = ea[e * 3] | (ea[e * 3 + 1] << 4) | (ea[e * 3 + 2] << 8);
}

// ---------------- weight prep + initial zeros ----------------
__global__ void wprep_all_kernel(const float* __restrict__ W1, const float* __restrict__ W2) {
    int i = blockIdx.x * blockDim.x + threadIdx.x;
    if (blockIdx.x == 0 && threadIdx.x < 512) g_s1[0][threadIdx.x] = 0.f;
    if (i < NN) g_cnt[i] = 0;
    int l = i >> 16;
    int j = i & 65535;
    if (j < 32768) {
        int   k = j >> 8;
        int   n = j & 255;
        float w = W1[l * 32768 + j];
        __nv_bfloat16 hb = __float2bfloat16(w);
        __nv_bfloat16 lb = __float2bfloat16(w - __bfloat162float(hb));
        g_w1h[l * 32768 + n * DD + k] = hb;
        g_w1l[l * 32768 + n * DD + k] = lb;
    } else {
        int   jj = j - 32768;
        int   k  = jj >> 7;
        int   n  = jj & 127;
        float w  = W2[l * 32768 + jj];
        __nv_bfloat16 hb = __float2bfloat16(w);
        __nv_bfloat16 lb = __float2bfloat16(w - __bfloat162float(hb));
        g_w2h[l * 32768 + n * D2 + k] = hb;
        g_w2l[l * 32768 + n * D2 + k] = lb;
    }
}

// ---------------- gather helper ----------------
__device__ __forceinline__ float4 bnrelu4(float4 h, float4 sc, float4 sh) {
    h.x = fmaxf(h.x * sc.x + sh.x, 0.f);
    h.y = fmaxf(h.y * sc.y + sh.y, 0.f);
    h.z = fmaxf(h.z * sc.z + sh.z, 0.f);
    h.w = fmaxf(h.w * sc.w + sh.w, 0.f);
    return h;
}

// =================================================================================
// GEMM1 (PERSISTENT fused gather + HMMA + LDSM), 512 threads — exact R15 winner.
// =================================================================================
#define SA1 136
#define G1_ALO 34816
#define G1_BHI 69632
#define G1_BLO 139264
#define G1_BOND 208896
#define G1_SC 221184
#define G1_SH 221696
#define G1_SMEM 222208

template <int APPLY_BN>
__global__ void __launch_bounds__(512, 1)
gemm1_tc(const float* __restrict__ bias, const float* __restrict__ eps_l,
         const float* __restrict__ bemb_l, const float* __restrict__ gp,
         const float* __restrict__ bp, int layer, int p) {
    extern __shared__ char sm[];
    __nv_bfloat16* sAh   = (__nv_bfloat16*)sm;
    __nv_bfloat16* sAl   = (__nv_bfloat16*)(sm + G1_ALO);
    __nv_bfloat16* sBh   = (__nv_bfloat16*)(sm + G1_BHI);
    __nv_bfloat16* sBl   = (__nv_bfloat16*)(sm + G1_BLO);
    float*         sbond = (float*)(sm + G1_BOND);
    float*         ssc   = (float*)(sm + G1_SC);
    float*         ssh   = (float*)(sm + G1_SH);

    const __nv_bfloat16* wh = g_w1h + layer * 32768;
    const __nv_bfloat16* wl = g_w1l + layer * 32768;

    const int t    = threadIdx.x;
    const int lane = t & 31;
    const int wid  = t >> 5;
    const int gid  = lane >> 2;
    const int q    = lane & 3;

    if (APPLY_BN && t < DD) {
        float mu   = g_s2[1 - p][t] * (1.f / NN);
        float var  = g_s2[1 - p][DD + t] * (1.f / NN) - mu * mu;
        float istd = rsqrtf(var + 1e-5f);
        float s    = gp[t] * istd;
        ssc[t]     = s;
        ssh[t]     = bp[t] - mu * s;
    }
    if (blockIdx.x == 0 && t < 256) g_s2[p][t] = 0.f;
    for (int i = t; i < 768; i += 512)
        ((float4*)sbond)[i] = ((const float4*)bemb_l)[i];

#pragma unroll
    for (int i = 0; i < 8; i++) {
        int idx = i * 512 + t;
        int n   = idx >> 4;
        int k0  = (idx & 15) * 8;
        *(uint4*)(sBh + n * SA1 + k0) = *(const uint4*)(wh + n * DD + k0);
        *(uint4*)(sBl + n * SA1 + k0) = *(const uint4*)(wl + n * DD + k0);
    }
    __syncthreads();

    const float* src = APPLY_BN ? g_v : g_h;
    float        ep  = 1.f + eps_l[0];
    float4       sc4, sh4;
    if (APPLY_BN) {
        sc4 = ((const float4*)ssc)[lane];
        sh4 = ((const float4*)ssh)[lane];
    }

    const int wm = wid & 3;
    const int wn = wid >> 2;

    const uint32_t sAh32 = (uint32_t)__cvta_generic_to_shared(sAh);
    const uint32_t sAl32 = (uint32_t)__cvta_generic_to_shared(sAl);
    const uint32_t sBh32 = (uint32_t)__cvta_generic_to_shared(sBh);
    const uint32_t sBl32 = (uint32_t)__cvta_generic_to_shared(sBl);
    const uint32_t aoff =
        (uint32_t)((wm * 32 + (lane & 15)) * SA1 * 2 + (((lane >> 4) << 3) * 2));
    const uint32_t boff =
        (uint32_t)((wn * 64 + (lane & 7) + (((lane >> 4) & 1) << 3)) * SA1 * 2 +
                   ((((lane >> 3) & 1) << 3) * 2));

#pragma unroll 1
    for (int tile = blockIdx.x; tile < MT1; tile += gridDim.x) {
        const int row0 = tile * 128;

#pragma unroll 1
        for (int j = 0; j < 8; j++) {
            int    r    = wid * 8 + j;
            int    node = row0 + r;
            float4 acc  = make_float4(0.f, 0.f, 0.f, 0.f);
            if (node < NN) {
                acc = ((const float4*)(src + (size_t)node * DD))[lane];
                if (APPLY_BN) acc = bnrelu4(acc, sc4, sh4);
                acc.x *= ep;
                acc.y *= ep;
                acc.z *= ep;
                acc.w *= ep;
                int start = g_rowptr[node];
                int deg   = g_cnt[node];
                int nb4   = deg >> 2;
                int cs[4], cb[4];
                if (nb4 > 0) {
#pragma unroll
                    for (int u = 0; u < 4; u++) {
                        cs[u] = g_csrc[start + u];
                        cb[u] = g_ca[start + u];
                    }
                }
#pragma unroll 1
                for (int b = 0; b < nb4; b++) {
                    int ns[4], na[4];
                    if (b + 1 < nb4) {
                        int o = start + (b + 1) * 4;
#pragma unroll
                        for (int u = 0; u < 4; u++) {
                            ns[u] = g_csrc[o + u];
                            na[u] = g_ca[o + u];
                        }
                    }
                    float4 hv[4];
#pragma unroll
                    for (int u = 0; u < 4; u++)
                        hv[u] = ((const float4*)(src + (size_t)cs[u] * DD))[lane];
#pragma unroll
                    for (int u = 0; u < 4; u++) {
                        float4 h = hv[u];
                        int    a = cb[u];
                        if (APPLY_BN) h = bnrelu4(h, sc4, sh4);
                        float4 e0 = ((const float4*)(sbond + (a & 15) * DD))[lane];
                        float4 e1 = ((const float4*)(sbond + (8 + ((a >> 4) & 15)) * DD))[lane];
                        float4 e2 = ((const float4*)(sbond + (16 + ((a >> 8) & 15)) * DD))[lane];
                        acc.x += fmaxf(h.x + e0.x + e1.x + e2.x, 0.f);
                        acc.y += fmaxf(h.y + e0.y + e1.y + e2.y, 0.f);
                        acc.z += fmaxf(h.z + e0.z + e1.z + e2.z, 0.f);
                        acc.w += fmaxf(h.w + e0.w + e1.w + e2.w, 0.f);
                    }
                    if (b + 1 < nb4) {
#pragma unroll
                        for (int u = 0; u < 4; u++) {
                            cs[u] = ns[u];
                            cb[u] = na[u];
                        }
                    }
                }
                for (int jj = nb4 * 4; jj < deg; jj++) {
                    int    s = g_csrc[start + jj];
                    int    a = g_ca[start + jj];
                    float4 h = ((const float4*)(src + (size_t)s * DD))[lane];
                    if (APPLY_BN) h = bnrelu4(h, sc4, sh4);
                    float4 e0 = ((const float4*)(sbond + (a & 15) * DD))[lane];
                    float4 e1 = ((const float4*)(sbond + (8 + ((a >> 4) & 15)) * DD))[lane];
                    float4 e2 = ((const float4*)(sbond + (16 + ((a >> 8) & 15)) * DD))[lane];
                    acc.x += fmaxf(h.x + e0.x + e1.x + e2.x, 0.f);
                    acc.y += fmaxf(h.y + e0.y + e1.y + e2.y, 0.f);
                    acc.z += fmaxf(h.z + e0.z + e1.z + e2.z, 0.f);
                    acc.w += fmaxf(h.w + e0.w + e1.w + e2.w, 0.f);
                }
            }
            uint2 hi, lo;
            split4(&acc.x, hi, lo);
            *(uint2*)(sAh + r * SA1 + lane * 4) = hi;
            *(uint2*)(sAl + r * SA1 + lane * 4) = lo;
        }
        __syncthreads();

        float acc[2][8][4];
#pragma unroll
        for (int m = 0; m < 2; m++)
#pragma unroll
            for (int nf = 0; nf < 8; nf++)
#pragma unroll
                for (int j = 0; j < 4; j++) acc[m][nf][j] = 0.f;

#pragma unroll
        for (int ks = 0; ks < 8; ks++) {
            uint32_t kb = (uint32_t)(ks * 32);
            uint32_t ah[2][4], al[2][4];
            ldsm4(ah[0], sAh32 + aoff + kb);
            ldsm4(ah[1], sAh32 + aoff + 16 * SA1 * 2 + kb);
            ldsm4(al[0], sAl32 + aoff + kb);
            ldsm4(al[1], sAl32 + aoff + 16 * SA1 * 2 + kb);
#pragma unroll
            for (int pp = 0; pp < 4; pp++) {
                uint32_t bh[4], bl[4];
                ldsm4(bh, sBh32 + boff + (uint32_t)(pp * 16 * SA1 * 2) + kb);
                ldsm4(bl, sBl32 + boff + (uint32_t)(pp * 16 * SA1 * 2) + kb);
#pragma unroll
                for (int m = 0; m < 2; m++) {
                    mma16816(acc[m][2 * pp], ah[m], bh);
                    mma16816(acc[m][2 * pp], ah[m], bl);
                    mma16816(acc[m][2 * pp], al[m], bh);
                    mma16816(acc[m][2 * pp + 1], ah[m], bh + 2);
                    mma16816(acc[m][2 * pp + 1], ah[m], bl + 2);
                    mma16816(acc[m][2 * pp + 1], al[m], bh + 2);
                }
            }
        }

#pragma unroll
        for (int nf = 0; nf < 8; nf++) {
            int    c  = wn * 64 + nf * 8 + q * 2;
            float2 b2 = *(const float2*)(bias + c);
            float  sx = 0.f, sy = 0.f, qx = 0.f, qy = 0.f;
#pragma unroll
            for (int m = 0; m < 2; m++) {
                int r = row0 + wm * 32 + m * 16 + gid;
                if (r < NN) {
                    float vx = acc[m][nf][0] + b2.x;
                    float vy = acc[m][nf][1] + b2.y;
                    *(float2*)(g_y + (size_t)r * D2 + c) = make_float2(vx, vy);
                    sx += vx; sy += vy; qx += vx * vx; qy += vy * vy;
                }
                if (r + 8 < NN) {
                    float vx = acc[m][nf][2] + b2.x;
                    float vy = acc[m][nf][3] + b2.y;
                    *(float2*)(g_y + (size_t)(r + 8) * D2 + c) = make_float2(vx, vy);
                    sx += vx; sy += vy; qx += vx * vx; qy += vy * vy;
                }
            }
#pragma unroll
            for (int o = 4; o < 32; o <<= 1) {
                sx += __shfl_xor_sync(0xffffffff, sx, o);
                sy += __shfl_xor_sync(0xffffffff, sy, o);
                qx += __shfl_xor_sync(0xffffffff, qx, o);
                qy += __shfl_xor_sync(0xffffffff, qy, o);
            }
            if (gid == 0) {
                atomicAdd(&g_s1[p][c], sx);
                atomicAdd(&g_s1[p][c + 1], sy);
                atomicAdd(&g_s1[p][D2 + c], qx);
                atomicAdd(&g_s1[p][D2 + c + 1], qy);
            }
        }
        __syncthreads();
    }
}

// =================================================================================
// GEMM2 (PERSISTENT K-split HMMA+LDSM): v = relu(bn1(y)) @ W2 + b2, stats -> g_s2[p].
// B_hi+B_lo staged ONCE per CTA; per tile: A staged per K-half, MMA, epilogue.
// smem: A_hi/A_lo [128][136] (34816 each), B_hi/B_lo [128][264] (67584 each) + consts.
// =================================================================================
#define SA2 264
#define SAH 136
#define G2_ALO 34816
#define G2_BHI 69632
#define G2_BLO 137216
#define G2_SC 204800
#define G2_SH 205824
#define G2_SMEM 206848

__global__ void __launch_bounds__(512, 1)
gemm2_tc(const float* __restrict__ bias, const float* __restrict__ g1p,
         const float* __restrict__ be1p, int layer, int p) {
    extern __shared__ char sm[];
    __nv_bfloat16* sAh = (__nv_bfloat16*)sm;
    __nv_bfloat16* sAl = (__nv_bfloat16*)(sm + G2_ALO);
    __nv_bfloat16* sBh = (__nv_bfloat16*)(sm + G2_BHI);
    __nv_bfloat16* sBl = (__nv_bfloat16*)(sm + G2_BLO);
    float*         sSC = (float*)(sm + G2_SC);
    float*         sSH = (float*)(sm + G2_SH);

    const __nv_bfloat16* wh = g_w2h + layer * 32768;
    const __nv_bfloat16* wl = g_w2l + layer * 32768;

    const int t    = threadIdx.x;
    const int lane = t & 31;
    const int wid  = t >> 5;
    const int gid  = lane >> 2;
    const int q    = lane & 3;

    if (t < 256) {
        float mu   = g_s1[p][t] * (1.f / NN);
        float var  = g_s1[p][D2 + t] * (1.f / NN) - mu * mu;
        float istd = rsqrtf(var + 1e-5f);
        float s    = g1p[t] * istd;
        sSC[t]     = s;
        sSH[t]     = be1p[t] - mu * s;
    }
    if (blockIdx.x == 0) g_s1[1 - p][t] = 0.f;

    // --- stage B_hi + B_lo once ---
#pragma unroll
    for (int i = 0; i < 8; i++) {
        int idx = i * 512 + t;
        int n   = idx >> 5;
        int k0  = (idx & 31) * 8;
        *(uint4*)(sBh + n * SA2 + k0) = *(const uint4*)(wh + n * D2 + k0);
        *(uint4*)(sBl + n * SA2 + k0) = *(const uint4*)(wl + n * D2 + k0);
    }
    __syncthreads();

    const int wm = wid & 3;
    const int wn = wid >> 2;

    const uint32_t sAh32 = (uint32_t)__cvta_generic_to_shared(sAh);
    const uint32_t sAl32 = (uint32_t)__cvta_generic_to_shared(sAl);
    const uint32_t sBh32 = (uint32_t)__cvta_generic_to_shared(sBh);
    const uint32_t sBl32 = (uint32_t)__cvta_generic_to_shared(sBl);
    const uint32_t aoff =
        (uint32_t)((wm * 32 + (lane & 15)) * SAH * 2 + (((lane >> 4) << 3) * 2));
    const uint32_t boff =
        (uint32_t)((wn * 32 + (lane & 7) + (((lane >> 4) & 1) << 3)) * SA2 * 2 +
                   ((((lane >> 3) & 1) << 3) * 2));

#pragma unroll 1
    for (int tile = blockIdx.x; tile < MT1; tile += gridDim.x) {
        const int row0 = tile * 128;

        float acc[2][4][4];
#pragma unroll
        for (int m = 0; m < 2; m++)
#pragma unroll
            for (int nf = 0; nf < 4; nf++)
#pragma unroll
                for (int j = 0; j < 4; j++) acc[m][nf][j] = 0.f;

#pragma unroll 1
        for (int half = 0; half < 2; half++) {
            // --- stage A half = relu(bn1(y))[:, half*128 .. +128] ---
            {
                int          r     = t >> 2;
                int          qq    = t & 3;
                const float* rp    = g_y + (size_t)(row0 + r) * D2 + half * 128;
                bool         valid = (row0 + r) < NN;
#pragma unroll
                for (int j = 0; j < 4; j++) {
                    int   k0 = qq * 32 + j * 8;
                    int   kg = half * 128 + k0;
                    float v[8];
                    if (valid) {
                        float4 a = ((const float4*)rp)[k0 >> 2];
                        float4 b = ((const float4*)rp)[(k0 >> 2) + 1];
                        float  raw[8] = {a.x, a.y, a.z, a.w, b.x, b.y, b.z, b.w};
#pragma unroll
                        for (int i = 0; i < 8; i++)
                            v[i] = fmaxf(raw[i] * sSC[kg + i] + sSH[kg + i], 0.f);
                    } else {
#pragma unroll
                        for (int i = 0; i < 8; i++) v[i] = 0.f;
                    }
                    uint4 hi, lo;
                    split8(v, hi, lo);
                    *(uint4*)(sAh + r * SAH + k0) = hi;
                    *(uint4*)(sAl + r * SAH + k0) = lo;
                }
            }
            __syncthreads();

#pragma unroll
            for (int ks = 0; ks < 8; ks++) {
                uint32_t kba = (uint32_t)(ks * 32);
                uint32_t kbb = (uint32_t)(half * 256 + ks * 32);
                uint32_t ah[2][4], al[2][4];
                ldsm4(ah[0], sAh32 + aoff + kba);
                ldsm4(ah[1], sAh32 + aoff + 16 * SAH * 2 + kba);
                ldsm4(al[0], sAl32 + aoff + kba);
                ldsm4(al[1], sAl32 + aoff + 16 * SAH * 2 + kba);
#pragma unroll
                for (int pp = 0; pp < 2; pp++) {
                    uint32_t bh[4], bl[4];
                    ldsm4(bh, sBh32 + boff + (uint32_t)(pp * 16 * SA2 * 2) + kbb);
                    ldsm4(bl, sBl32 + boff + (uint32_t)(pp * 16 * SA2 * 2) + kbb);
#pragma unroll
                    for (int m = 0; m < 2; m++) {
                        mma16816(acc[m][2 * pp], ah[m], bh);
                        mma16816(acc[m][2 * pp], ah[m], bl);
                        mma16816(acc[m][2 * pp], al[m], bh);
                        mma16816(acc[m][2 * pp + 1], ah[m], bh + 2);
                        mma16816(acc[m][2 * pp + 1], ah[m], bl + 2);
                        mma16816(acc[m][2 * pp + 1], al[m], bh + 2);
                    }
                }
            }
            __syncthreads();
        }

        // --- epilogue + fused column stats -> g_s2[p] ---
#pragma unroll
        for (int nf = 0; nf < 4; nf++) {
            int    c  = wn * 32 + nf * 8 + q * 2;
            float2 b2 = *(const float2*)(bias + c);
            float  sx = 0.f, sy = 0.f, qx = 0.f, qy = 0.f;
#pragma unroll
            for (int m = 0; m < 2; m++) {
                int r = row0 + wm * 32 + m * 16 + gid;
                if (r < NN) {
                    float vx = acc[m][nf][0] + b2.x;
                    float vy = acc[m][nf][1] + b2.y;
                    *(float2*)(g_v + (size_t)r * DD + c) = make_float2(vx, vy);
                    sx += vx; sy += vy; qx += vx * vx; qy += vy * vy;
                }
                if (r + 8 < NN) {
                    float vx = acc[m][nf][2] + b2.x;
                    float vy = acc[m][nf][3] + b2.y;
                    *(float2*)(g_v + (size_t)(r + 8) * DD + c) = make_float2(vx, vy);
                    sx += vx; sy += vy; qx += vx * vx; qy += vy * vy;
                }
            }
#pragma unroll
            for (int o = 4; o < 32; o <<= 1) {
                sx += __shfl_xor_sync(0xffffffff, sx, o);
                sy += __shfl_xor_sync(0xffffffff, sy, o);
                qx += __shfl_xor_sync(0xffffffff, qx, o);
                qy += __shfl_xor_sync(0xffffffff, qy, o);
            }
            if (gid == 0) {
                atomicAdd(&g_s2[p][c], sx);
                atomicAdd(&g_s2[p][c + 1], sy);
                atomicAdd(&g_s2[p][DD + c], qx);
                atomicAdd(&g_s2[p][DD + c + 1], qy);
            }
        }
    }
}

// ---------------- final output ----------------
__global__ void norm_out_kernel(float* __restrict__ out, const float* __restrict__ gp,
                                const float* __restrict__ bp, int p) {
    __shared__ float ssc[DD], ssh[DD];
    int t = threadIdx.x;
    if (t < DD) {
        float mu   = g_s2[p][t] * (1.f / NN);
        float var  = g_s2[p][DD + t] * (1.f / NN) - mu * mu;
        float istd = rsqrtf(var + 1e-5f);
        float s    = gp[t] * istd;
        ssc[t]     = s;
        ssh[t]     = bp[t] - mu * s;
    }
    __syncthreads();
    const int total4 = NN * DD / 4;
    for (int i = blockIdx.x * blockDim.x + t; i < total4; i += gridDim.x * blockDim.x) {
        int    c4 = i & 31;
        float4 v  = ((const float4*)g_v)[i];
        float4 sc = ((const float4*)ssc)[c4];
        float4 sh = ((const float4*)ssh)[c4];
        v.x = v.x * sc.x + sh.x;
        v.y = v.y * sc.y + sh.y;
        v.z = v.z * sc.z + sh.z;
        v.w = v.w * sc.w + sh.w;
        ((float4*)out)[i] = v;
    }
}

// ---------------- launch ----------------
extern "C" void kernel_launch(void* const* d_in, const int* in_sizes, int n_in,
                              void* d_out, int out_size) {
    const int*   x    = (const int*)d_in[0];
    const int*   ei   = (const int*)d_in[1];
    const int*   ea   = (const int*)d_in[2];
    const float* aemb = (const float*)d_in[3];
    const float* bemb = (const float*)d_in[4];
    const float* W1   = (const float*)d_in[5];
    const float* b1   = (const float*)d_in[6];
    const float* g1   = (const float*)d_in[7];
    const float* be1  = (const float*)d_in[8];
    const float* W2   = (const float*)d_in[9];
    const float* b2   = (const float*)d_in[10];
    const float* eps  = (const float*)d_in[11];
    const float* gout = (const float*)d_in[12];
    const float* beo  = (const float*)d_in[13];
    float*       out  = (float*)d_out;

    cudaFuncSetAttribute(gemm1_tc<0>, cudaFuncAttributeMaxDynamicSharedMemorySize, G1_SMEM);
    cudaFuncSetAttribute(gemm1_tc<1>, cudaFuncAttributeMaxDynamicSharedMemorySize, G1_SMEM);
    cudaFuncSetAttribute(gemm2_tc, cudaFuncAttributeMaxDynamicSharedMemorySize, G2_SMEM);

    atom_enc_kernel<<<(NN * DD) / 256, 256>>>(x, aemb);
    wprep_all_kernel<<<640, 512>>>(W1, W2);

    const int NB = (NN + 511) / 512;
    hist_kernel<<<(NE + 255) / 256, 256>>>(ei);
    scan1_kernel<<<NB, 512>>>();
    scan3_kernel<<<(NN + 255) / 256, 256>>>();
    fill_kernel<<<(NE + 255) / 256, 256>>>(ei, ea);

    for (int l = 0; l < NL; l++) {
        int p = l & 1;
        if (l == 0)
            gemm1_tc<0><<<PGRID, 512, G1_SMEM>>>(b1, eps, bemb, nullptr, nullptr, 0, 0);
        else
            gemm1_tc<1><<<PGRID, 512, G1_SMEM>>>(b1 + l * D2, eps + l,
                                                 bemb + l * 3 * 8 * DD,
                                                 gout + (l - 1) * DD, beo + (l - 1) * DD,
                                                 l, p);
        gemm2_tc<<<PGRID, 512, G2_SMEM>>>(b2 + l * DD, g1 + l * D2, be1 + l * D2, l, p);
    }
    norm_out_kernel<<<256, 256>>>(out, gout + (NL - 1) * DD, beo + (NL - 1) * DD,
                                  (NL - 1) & 1);
}